// round 12
// baseline (speedup 1.0000x reference)
#include <cuda_runtime.h>
#include <cstdint>
#include <cstddef>

#define BATCH 8
#define P 2048
#define D 64
#define FEPS 0.1f
// log2(e)/eps
#define INV 14.426950408889634f
// eps*ln(2)
#define EPSLN2 0.06931471805599453f
#define NMAT ((size_t)BATCH * P * P)
#define NT4 4096             // 4-row tiles per pass
#define NBLK 148             // persistent blocks (1 per SM)
#define TILE_BYTES 32768u    // 4 rows * 2048 * 4B
#define NSTAGE 5
#define NCW 16               // consumer warps
#define THREADS 544          // 16 consumer warps + 1 producer warp
#define GATE 30.0f

// ---------------- scratch (static device globals; no runtime allocation) ----
__device__ __align__(16) float g_u[BATCH * P];
__device__ __align__(16) float g_v[BATCH * P];
__device__ float g_xn[BATCH * P];
__device__ float g_yn[BATCH * P];
__device__ float g_errp[BATCH * P];      // per-row |du|
__device__ float g_costp[BATCH * P];     // per-row pi*C partials
__device__ int   g_done[2];              // parity double-buffered freeze flag
__device__ __align__(16) float4 g_ct4[NMAT / 4];  // C transposed (134MB scratch)

__device__ __forceinline__ float ex2f(float x) {
    float r; asm("ex2.approx.f32 %0, %1;" : "=f"(r) : "f"(x)); return r;
}
__device__ __forceinline__ float lg2f_(float x) {
    float r; asm("lg2.approx.f32 %0, %1;" : "=f"(r) : "f"(x)); return r;
}
__device__ __forceinline__ float eps_log_marginal() {
    return FEPS * logf(1.0f / 2048.0f + 1e-8f);
}
__device__ __forceinline__ uint32_t smem_u32(const void* p) {
    return (uint32_t)__cvta_generic_to_shared(p);
}
__device__ __forceinline__ void mbar_wait(uint32_t mbar, uint32_t phase) {
    asm volatile(
        "{\n\t.reg .pred P;\n\t"
        "W%=: mbarrier.try_wait.parity.acquire.cta.shared::cta.b64 P, [%0], %1;\n\t"
        "@!P bra W%=;\n\t}"
        :: "r"(mbar), "r"(phase) : "memory");
}
__device__ __forceinline__ void mbar_arrive(uint32_t mbar) {
    asm volatile("mbarrier.arrive.shared.b64 _, [%0];" :: "r"(mbar) : "memory");
}
__device__ __forceinline__ void issue_copy(uint32_t smem_dst, const void* src, uint32_t mbar) {
    asm volatile("mbarrier.arrive.expect_tx.shared.b64 _, [%0], %1;"
                 :: "r"(mbar), "r"(TILE_BYTES) : "memory");
    asm volatile("cp.async.bulk.shared::cta.global.mbarrier::complete_tx::bytes "
                 "[%0], [%1], %2, [%3];"
                 :: "r"(smem_dst), "l"(src), "r"(TILE_BYTES), "r"(mbar) : "memory");
}

// ---------------- init --------------------------------------------------------
__global__ void k_init() {
    int i = blockIdx.x * blockDim.x + threadIdx.x;
    if (i < BATCH * P) { g_u[i] = 0.0f; g_v[i] = 0.0f; }
    if (i == 0) { g_done[0] = 0; g_done[1] = 0; }
}

// ---------------- squared norms (warp per point) ------------------------------
__global__ void k_norm(const float* __restrict__ x, const float* __restrict__ y) {
    int gw   = (blockIdx.x * blockDim.x + threadIdx.x) >> 5;
    int lane = threadIdx.x & 31;
    if (gw >= 2 * BATCH * P) return;
    bool isx = gw < BATCH * P;
    int p = isx ? gw : gw - BATCH * P;
    const float* src = isx ? x : y;
    float a0 = src[(size_t)p * D + lane];
    float a1 = src[(size_t)p * D + 32 + lane];
    float s = a0 * a0 + a1 * a1;
    #pragma unroll
    for (int o = 16; o; o >>= 1) s += __shfl_xor_sync(0xffffffffu, s, o);
    if (lane == 0) (isx ? g_xn : g_yn)[p] = s;
}

// ---------------- C = ||x||^2 + ||y||^2 - 2 x.y  (+ transposed copy) ----------
__global__ void k_costmat(const float* __restrict__ x, const float* __restrict__ y,
                          float* __restrict__ Cout) {
    __shared__ float xs[64][65];
    __shared__ float ys[64][65];
    int b  = blockIdx.z;
    int i0 = blockIdx.y * 64;
    int j0 = blockIdx.x * 64;
    int tid = threadIdx.x;

    const float* xb = x + ((size_t)b * P + i0) * D;
    const float* yb = y + ((size_t)b * P + j0) * D;
    #pragma unroll
    for (int idx = tid; idx < 4096; idx += 256) {
        int p = idx >> 6, d = idx & 63;
        xs[d][p] = xb[(size_t)p * D + d];
        ys[d][p] = yb[(size_t)p * D + d];
    }
    __syncthreads();

    int tx = tid & 15, ty = tid >> 4;
    float acc[4][4];
    #pragma unroll
    for (int r = 0; r < 4; r++)
        #pragma unroll
        for (int c = 0; c < 4; c++) acc[r][c] = 0.0f;

    #pragma unroll 8
    for (int k = 0; k < 64; k++) {
        float rx[4], ry[4];
        #pragma unroll
        for (int r = 0; r < 4; r++) rx[r] = xs[k][ty * 4 + r];
        #pragma unroll
        for (int c = 0; c < 4; c++) ry[c] = ys[k][tx * 4 + c];
        #pragma unroll
        for (int r = 0; r < 4; r++)
            #pragma unroll
            for (int c = 0; c < 4; c++) acc[r][c] = fmaf(rx[r], ry[c], acc[r][c]);
    }

    float xnr[4], ynr[4];
    #pragma unroll
    for (int r = 0; r < 4; r++) xnr[r] = g_xn[b * P + i0 + ty * 4 + r];
    #pragma unroll
    for (int c = 0; c < 4; c++) ynr[c] = g_yn[b * P + j0 + tx * 4 + c];

    float val[4][4];
    #pragma unroll
    for (int r = 0; r < 4; r++)
        #pragma unroll
        for (int c = 0; c < 4; c++)
            val[r][c] = xnr[r] + ynr[c] - 2.0f * acc[r][c];

    #pragma unroll
    for (int r = 0; r < 4; r++) {
        int row = i0 + ty * 4 + r;
        float4 v4 = make_float4(val[r][0], val[r][1], val[r][2], val[r][3]);
        *reinterpret_cast<float4*>(Cout + ((size_t)b * P + row) * P + j0 + tx * 4) = v4;
    }

    __syncthreads();
    #pragma unroll
    for (int r = 0; r < 4; r++)
        #pragma unroll
        for (int c = 0; c < 4; c++)
            xs[ty * 4 + r][tx * 4 + c] = val[r][c];
    __syncthreads();
    float* CT = (float*)g_ct4;
    #pragma unroll
    for (int idx = tid; idx < 4096; idx += 256) {
        int jj = idx >> 6, ii = idx & 63;
        CT[((size_t)b * P + (j0 + jj)) * P + (i0 + ii)] = xs[ii][jj];
    }
}

// ---------------- warp-specialized persistent row-LSE pass --------------------
// 148 blocks, 544 threads: 16 consumer warps (4 per row, quarter-row each over
// 4-row/32KB tiles) + 1 producer warp driving a 5-stage bulk-copy pipeline via
// full/empty mbarriers. No block-wide syncs in the loop; row combines use
// 128-thread named barriers.
template<bool UPASS>
__global__ void __launch_bounds__(THREADS, 1) k_lse_pipe(const float* __restrict__ Cg, int par) {
    if (g_done[par]) {
        if (!UPASS && blockIdx.x == 0 && threadIdx.x == 0) g_done[par ^ 1] = 1;
        return;
    }
    const float* M    = UPASS ? Cg : (const float*)g_ct4;
    const float* wv   = UPASS ? g_v : g_u;
    float*       outv = UPASS ? g_u : g_v;

    extern __shared__ __align__(128) float tile[];      // NSTAGE * 8192 floats
    __shared__ float sm[NCW];     // per-quarter-warp max
    __shared__ float ss[NCW];     // per-quarter-warp sum
    __shared__ float red[20];
    __shared__ __align__(8) unsigned long long mbars[2 * NSTAGE];  // full[5], empty[5]

    int tid = threadIdx.x, lane = tid & 31, warp = tid >> 5;
    int t0 = (int)(((long long)blockIdx.x * NT4) / NBLK);
    int t1 = (int)(((long long)(blockIdx.x + 1) * NT4) / NBLK);

    uint32_t fullb  = smem_u32(&mbars[0]);
    uint32_t emptyb = smem_u32(&mbars[NSTAGE]);
    if (tid == 0) {
        #pragma unroll
        for (int s = 0; s < NSTAGE; s++) {
            asm volatile("mbarrier.init.shared.b64 [%0], 1;"  :: "r"(fullb  + 8 * s) : "memory");
            asm volatile("mbarrier.init.shared.b64 [%0], %1;" :: "r"(emptyb + 8 * s), "r"(NCW) : "memory");
        }
    }
    __syncthreads();

    // v-pass block 0: fold convergence check (g_errp complete from u-kernel)
    if (!UPASS && blockIdx.x == 0) {
        float e = 0.0f;
        for (int t = tid; t < BATCH * P; t += THREADS) e += g_errp[t];
        #pragma unroll
        for (int o = 16; o; o >>= 1) e += __shfl_xor_sync(0xffffffffu, e, o);
        if (lane == 0) red[warp] = e;
        __syncthreads();
        if (tid == 0) {
            float tot = 0.0f;
            #pragma unroll
            for (int i2 = 0; i2 < 17; i2++) tot += red[i2];
            g_done[par ^ 1] = (tot * (1.0f / BATCH) < 0.1f) ? 1 : 0;
        }
    }

    // ---------------- producer warp ----------------
    if (warp == NCW) {
        if (lane == 0) {
            int pp[NSTAGE];
            #pragma unroll
            for (int s = 0; s < NSTAGE; s++) pp[s] = 1;   // first waits pass immediately
            for (int k = t0; k < t1; k++) {
                int s = (k - t0) % NSTAGE;
                mbar_wait(emptyb + 8 * s, (uint32_t)pp[s]);
                pp[s] ^= 1;
                issue_copy(smem_u32(tile) + s * TILE_BYTES,
                           M + (size_t)k * (4 * P), fullb + 8 * s);
            }
        }
        return;
    }

    // ---------------- consumer warps ----------------
    int row4 = warp >> 2;          // 0..3 : row within tile
    int quart = warp & 3;          // 0..3 : quarter of the row
    int barid = row4 + 1;          // named barriers 1..4, 128 threads each

    float4 tv[4];                  // dual vector * INV : this lane's 16 j's
    int cur_b = -1;
    int phase[NSTAGE];
    #pragma unroll
    for (int s = 0; s < NSTAGE; s++) phase[s] = 0;

    for (int k = t0; k < t1; k++) {
        int b = k >> 9;                          // 512 4-row tiles per batch
        if (b != cur_b) {
            const float4* vb4 = reinterpret_cast<const float4*>(wv + b * P);
            #pragma unroll
            for (int q = 0; q < 4; q++) {
                float4 t = vb4[quart * 128 + lane + 32 * q];
                tv[q] = make_float4(t.x * INV, t.y * INV, t.z * INV, t.w * INV);
            }
            cur_b = b;
        }

        int s = (k - t0) % NSTAGE;
        mbar_wait(fullb + 8 * s, (uint32_t)phase[s]);
        phase[s] ^= 1;

        const float4* R = reinterpret_cast<const float4*>(tile + s * 8192)
                          + row4 * 512 + quart * 128;

        // pass 1: single smem read pass; w kept in registers
        float w[16];
        float lm = -3.4e38f;
        #pragma unroll
        for (int q = 0; q < 4; q++) {
            float4 c = R[lane + q * 32];
            float4 t = tv[q];
            float w0 = fmaf(c.x, -INV, t.x);
            float w1 = fmaf(c.y, -INV, t.y);
            float w2 = fmaf(c.z, -INV, t.z);
            float w3 = fmaf(c.w, -INV, t.w);
            w[4 * q + 0] = w0; w[4 * q + 1] = w1;
            w[4 * q + 2] = w2; w[4 * q + 3] = w3;
            lm = fmaxf(lm, fmaxf(fmaxf(w0, w1), fmaxf(w2, w3)));
        }
        // stage consumed (values in registers) -> release it to the producer
        if (lane == 0) mbar_arrive(emptyb + 8 * s);

        float mh = lm;
        #pragma unroll
        for (int o = 16; o; o >>= 1) mh = fmaxf(mh, __shfl_xor_sync(0xffffffffu, mh, o));
        if (lane == 0) sm[warp] = mh;
        asm volatile("bar.sync %0, 128;" :: "r"(barid) : "memory");

        int gb = row4 * 4;
        float m = fmaxf(fmaxf(sm[gb], sm[gb + 1]), fmaxf(sm[gb + 2], sm[gb + 3]));

        // pass 2: EX2 from registers, only in quarter-warps containing candidates
        float ls = 0.0f;
        if (lm > m - GATE) {
            #pragma unroll
            for (int i = 0; i < 16; i++) ls += ex2f(w[i] - m);
        }
        #pragma unroll
        for (int o = 16; o; o >>= 1) ls += __shfl_xor_sync(0xffffffffu, ls, o);
        if (lane == 0) ss[warp] = ls;
        asm volatile("bar.sync %0, 128;" :: "r"(barid) : "memory");

        if (quart == 0 && lane == 0) {
            float tot = ss[gb] + ss[gb + 1] + ss[gb + 2] + ss[gb + 3];
            float nv = eps_log_marginal() - EPSLN2 * (m + lg2f_(tot));
            int r = k * 4 + row4;
            if (UPASS) {
                float old = outv[r];
                outv[r] = nv;
                g_errp[r] = fabsf(nv - old);
            } else {
                outv[r] = nv;
            }
        }
    }
}

// ---------------- pi = exp((u+v-C)/eps), partial cost -------------------------
__global__ void __launch_bounds__(256) k_pi(const float4* __restrict__ C4,
                                            float4* __restrict__ pi4) {
    __shared__ __align__(16) float uvw[2048];
    __shared__ float sacc[256];
    int r = blockIdx.x, b = r >> 11, tid = threadIdx.x;
    float ug = g_u[r] * INV;
    for (int j = tid; j < 2048; j += 256) uvw[j] = fmaf(g_v[b * P + j], INV, ug);
    __syncthreads();

    const float4* Crow = C4 + (size_t)r * 512;
    float4* prow = pi4 + (size_t)r * 512;
    const float4* uvw4 = reinterpret_cast<const float4*>(uvw);
    float acc = 0.0f;
    #pragma unroll 2
    for (int j4 = tid; j4 < 512; j4 += 256) {
        float4 c = Crow[j4];
        float4 t = uvw4[j4];
        float4 p;
        p.x = ex2f(fmaf(c.x, -INV, t.x));
        p.y = ex2f(fmaf(c.y, -INV, t.y));
        p.z = ex2f(fmaf(c.z, -INV, t.z));
        p.w = ex2f(fmaf(c.w, -INV, t.w));
        prow[j4] = p;
        acc = fmaf(p.x, c.x, fmaf(p.y, c.y, fmaf(p.z, c.z, fmaf(p.w, c.w, acc))));
    }
    sacc[tid] = acc;
    __syncthreads();
    for (int o = 128; o; o >>= 1) {
        if (tid < o) sacc[tid] += sacc[tid + o];
        __syncthreads();
    }
    if (tid == 0) g_costp[r] = sacc[0];
}

__global__ void k_costred(float* __restrict__ costOut) {
    __shared__ float sb[256];
    int b = blockIdx.x;
    float e = 0.0f;
    for (int t = threadIdx.x; t < P; t += 256) e += g_costp[b * P + t];
    sb[threadIdx.x] = e;
    __syncthreads();
    for (int o = 128; o; o >>= 1) {
        if (threadIdx.x < o) sb[threadIdx.x] += sb[threadIdx.x + o];
        __syncthreads();
    }
    if (threadIdx.x == 0) costOut[b] = sb[0];
}

// ---------------- launch ------------------------------------------------------
extern "C" void kernel_launch(void* const* d_in, const int* in_sizes, int n_in,
                              void* d_out, int out_size) {
    (void)in_sizes; (void)n_in; (void)out_size;
    const float* x = (const float*)d_in[0];
    const float* y = (const float*)d_in[1];
    float* out  = (float*)d_out;
    float* cost = out;                      // [8]
    float* pi   = out + 8;                  // [8,2048,2048]
    float* Cm   = out + 8 + NMAT;           // [8,2048,2048]

    cudaFuncSetAttribute(k_lse_pipe<true>,
                         cudaFuncAttributeMaxDynamicSharedMemorySize, NSTAGE * (int)TILE_BYTES);
    cudaFuncSetAttribute(k_lse_pipe<false>,
                         cudaFuncAttributeMaxDynamicSharedMemorySize, NSTAGE * (int)TILE_BYTES);

    k_init<<<64, 256>>>();
    k_norm<<<4096, 256>>>(x, y);
    dim3 cg(32, 32, 8);
    k_costmat<<<cg, 256>>>(x, y, Cm);

    for (int k = 0; k < 100; k++) {
        int par = k & 1;
        k_lse_pipe<true ><<<NBLK, THREADS, NSTAGE * TILE_BYTES>>>(Cm, par);  // u (rows of C)
        k_lse_pipe<false><<<NBLK, THREADS, NSTAGE * TILE_BYTES>>>(Cm, par);  // v (rows of C^T)
    }

    k_pi<<<16384, 256>>>((const float4*)Cm, (float4*)pi);
    k_costred<<<8, 256>>>(cost);
}